// round 14
// baseline (speedup 1.0000x reference)
#include <cuda_runtime.h>
#include <cuda_fp16.h>
#include <cstdint>

#define SQ    2048
#define DM    512
#define NH    8
#define DEP   64
#define BATCH 2
#define NTOK  (BATCH*SQ)
#define NBH   (BATCH*NH)

// ---------------- device scratch (fp16) ----------------
__device__ __half g_xq[NTOK*DM], g_xk[NTOK*DM], g_xv[NTOK*DM];
__device__ __half g_wq[DM*DM];
__device__ __half g_wk[DM*DM];
__device__ __half g_wv[DM*DM];
__device__ __half g_wf[DM*DM];
__device__ __half g_Q[NBH*SQ*DEP];   // pre-scaled log2e/8
__device__ __half g_K[NBH*SQ*DEP];   // pos folded in
__device__ __half g_V[NBH*SQ*DEP];
__device__ __half g_AO[NTOK*DM];

// ---------------- helpers ----------------
static __device__ __forceinline__ uint32_t smem_u32(const void* p) {
    uint32_t a;
    asm("{ .reg .u64 t; cvta.to.shared.u64 t, %1; cvt.u32.u64 %0, t; }" : "=r"(a) : "l"(p));
    return a;
}
static __device__ __forceinline__ uint32_t swz(uint32_t b) { return b ^ ((b >> 3) & 0x70); }

static __device__ __forceinline__ void cp16(uint32_t dst, const void* src) {
    asm volatile("cp.async.cg.shared.global [%0], [%1], 16;" :: "r"(dst), "l"(src));
}
#define CP_COMMIT() asm volatile("cp.async.commit_group;" ::: "memory")
#define CP_WAIT0()  asm volatile("cp.async.wait_group 0;" ::: "memory")
#define CP_WAIT1()  asm volatile("cp.async.wait_group 1;" ::: "memory")

static __device__ __forceinline__ void ldsm4(uint32_t& r0, uint32_t& r1, uint32_t& r2, uint32_t& r3, uint32_t a) {
    asm volatile("ldmatrix.sync.aligned.m8n8.x4.shared.b16 {%0,%1,%2,%3}, [%4];"
                 : "=r"(r0), "=r"(r1), "=r"(r2), "=r"(r3) : "r"(a));
}
static __device__ __forceinline__ void ldsm4t(uint32_t& r0, uint32_t& r1, uint32_t& r2, uint32_t& r3, uint32_t a) {
    asm volatile("ldmatrix.sync.aligned.m8n8.x4.trans.shared.b16 {%0,%1,%2,%3}, [%4];"
                 : "=r"(r0), "=r"(r1), "=r"(r2), "=r"(r3) : "r"(a));
}
static __device__ __forceinline__ void mmah(float* c, const uint32_t* a, uint32_t b0, uint32_t b1) {
    asm volatile("mma.sync.aligned.m16n8k16.row.col.f32.f16.f16.f32 "
                 "{%0,%1,%2,%3}, {%4,%5,%6,%7}, {%8,%9}, {%0,%1,%2,%3};"
                 : "+f"(c[0]), "+f"(c[1]), "+f"(c[2]), "+f"(c[3])
                 : "r"(a[0]), "r"(a[1]), "r"(a[2]), "r"(a[3]), "r"(b0), "r"(b1));
}
static __device__ __forceinline__ uint32_t addrA(uint32_t base, int row0, int col0, int lid) {
    int quad = lid >> 3, sub = lid & 7;
    int row = row0 + sub + ((quad & 1) << 3);
    int col = col0 + ((quad >> 1) << 3);
    return base + swz((uint32_t)(row * 128 + col * 2));
}
static __device__ __forceinline__ uint32_t addrB(uint32_t base, int row0, int col0, int lid) {
    int quad = lid >> 3, sub = lid & 7;
    int row = row0 + sub + ((quad >> 1) << 3);
    int col = col0 + ((quad & 1) << 3);
    return base + swz((uint32_t)(row * 128 + col * 2));
}
static __device__ __forceinline__ uint32_t pkh2(float v0, float v1) {
    __half2 h = __floats2half2_rn(v0, v1);
    return *(uint32_t*)&h;
}
static __device__ __forceinline__ uint32_t ex2h2(uint32_t x) {
    uint32_t r; asm("ex2.approx.f16x2 %0, %1;" : "=r"(r) : "r"(x)); return r;
}
// async copy [rows x 64] fp16 into SW128 smem tile (128B rows); 128 threads
static __device__ __forceinline__ void tile_async(uint32_t dst, const __half* src,
                                                  int ldsrc, int tid, int rows) {
    int iters = rows * 8 / 128;
#pragma unroll
    for (int i = 0; i < iters; i++) {
        int g = i * 128 + tid;
        int row = g >> 3, c16 = g & 7;
        cp16(dst + swz((uint32_t)(row * 128 + c16 * 16)), src + (size_t)row * ldsrc + c16 * 8);
    }
}

// ---------------- fp32 -> fp16 conversions (single launch) ----------------
__global__ void split_all(const float* __restrict__ q, const float* __restrict__ k,
                          const float* __restrict__ v, const float* __restrict__ wq,
                          const float* __restrict__ wk, const float* __restrict__ wv,
                          const float* __restrict__ wf) {
    int which = blockIdx.y;
    int i = blockIdx.x * blockDim.x + threadIdx.x;
    const float* x;
    __half* dst;
    int n4;
    switch (which) {
        case 0: x = q;  dst = g_xq; n4 = NTOK * DM / 4; break;
        case 1: x = k;  dst = g_xk; n4 = NTOK * DM / 4; break;
        case 2: x = v;  dst = g_xv; n4 = NTOK * DM / 4; break;
        case 3: x = wq; dst = g_wq; n4 = DM * DM / 4; break;
        case 4: x = wk; dst = g_wk; n4 = DM * DM / 4; break;
        case 5: x = wv; dst = g_wv; n4 = DM * DM / 4; break;
        default: x = wf; dst = g_wf; n4 = DM * DM / 4; break;
    }
    if (i < n4) {
        float4 v4 = ((const float4*)x)[i];
        uint2 h;
        h.x = pkh2(v4.x, v4.y);
        h.y = pkh2(v4.z, v4.w);
        ((uint2*)dst)[i] = h;
    }
}

// ---------------- projection GEMM: M64 x N64 tiles, warp = 16 rows x 64 cols ----------------
// stage: A +0 (8K), B +8192 (8K); 16K/stage, double-buffered; 4 CTA/SM
#define P_STAGE 16384
#define P_TOT   (2*P_STAGE)

__global__ __launch_bounds__(128, 4) void proj_mma(
    const float* __restrict__ b1, const float* __restrict__ b2,
    const float* __restrict__ b3, const float* __restrict__ pos,
    float* __restrict__ outf, int mode_base)
{
    extern __shared__ char sm[];
    uint32_t sb = smem_u32(sm);
    int tid = threadIdx.x, wid = tid >> 5, lid = tid & 31;
    int m0 = blockIdx.y * 64, n0 = blockIdx.x * 64;
    int mode = mode_base ? (mode_base + (int)blockIdx.z) : 0;

    const __half *A, *B;
    const float* bias;
    switch (mode) {
        case 0: A = g_AO; B = g_wf; bias = b1; break;
        case 1: A = g_xq; B = g_wq; bias = b1; break;
        case 2: A = g_xk; B = g_wk; bias = b2; break;
        default: A = g_xv; B = g_wv; bias = b3; break;
    }

    float acc[8][4];
#pragma unroll
    for (int nt = 0; nt < 8; nt++)
#pragma unroll
        for (int r = 0; r < 4; r++) acc[nt][r] = 0.f;

    tile_async(sb + 0,    A + (size_t)m0 * DM, DM, tid, 64);
    tile_async(sb + 8192, B + (size_t)n0 * DM, DM, tid, 64);
    CP_COMMIT();
    CP_WAIT0();
    __syncthreads();

    for (int c = 0; c < 8; c++) {
        uint32_t cur = sb + (uint32_t)(c & 1) * P_STAGE;
        if (c < 7) {
            uint32_t nxt = sb + (uint32_t)((c + 1) & 1) * P_STAGE;
            int k1 = (c + 1) * 64;
            tile_async(nxt + 0,    A + (size_t)m0 * DM + k1, DM, tid, 64);
            tile_async(nxt + 8192, B + (size_t)n0 * DM + k1, DM, tid, 64);
            CP_COMMIT();
        }

#pragma unroll
        for (int ks = 0; ks < 4; ks++) {
            int kc = ks * 16;
            uint32_t ah[4];
            ldsm4(ah[0], ah[1], ah[2], ah[3], addrA(cur + 0, wid * 16, kc, lid));
            uint32_t bh[16];
#pragma unroll
            for (int hf = 0; hf < 4; hf++)
                ldsm4(bh[hf * 4], bh[hf * 4 + 1], bh[hf * 4 + 2], bh[hf * 4 + 3],
                      addrB(cur + 8192, hf * 16, kc, lid));
#pragma unroll
            for (int nt = 0; nt < 8; nt++)
                mmah(acc[nt], ah, bh[nt * 2], bh[nt * 2 + 1]);
        }
        if (c < 7) {
            CP_WAIT0();
            __syncthreads();
        }
    }

    const float SC = 0.180336880111120429f;  // log2(e)/8
    int r0g = m0 + wid * 16 + (lid >> 2);
#pragma unroll
    for (int nt = 0; nt < 8; nt++) {
        int og = n0 + nt * 8 + ((lid & 3) << 1);
        float b0 = bias[og], b1v = bias[og + 1];
#pragma unroll
        for (int half = 0; half < 2; half++) {
            int n = r0g + half * 8;
            float v0 = acc[nt][half * 2]     + b0;
            float v1 = acc[nt][half * 2 + 1] + b1v;
            if (mode == 0) {
                outf[(size_t)n * DM + og]     = v0;
                outf[(size_t)n * DM + og + 1] = v1;
            } else {
                int bb = n >> 11, s = n & (SQ - 1);
                int h = og >> 6, d = og & 63;
                if (mode == 2) { v0 += pos[s * DEP + d]; v1 += pos[s * DEP + d + 1]; }
                if (mode == 1) { v0 *= SC; v1 *= SC; }
                size_t idx = ((((size_t)(bb * NH + h) * SQ) + s) * DEP + d) >> 1;
                __half* dst = (mode == 1) ? g_Q : ((mode == 2) ? g_K : g_V);
                ((uint32_t*)dst)[idx] = pkh2(v0, v1);
            }
        }
    }
}

// ---------------- flash attention: R12 version (3-stage, 3 CTA/SM) ----------------
#define A_SSZ 16384
#define A_TOT (3*A_SSZ)
#define KT 64
#define ONES2 0x3C003C00u   // (1.0h, 1.0h)

__global__ __launch_bounds__(128, 3) void attn_mma() {
    extern __shared__ char sm[];
    uint32_t sb = smem_u32(sm);
    int tid = threadIdx.x, wid = tid >> 5, lid = tid & 31;
    int bh = blockIdx.y, q0 = blockIdx.x * 64;
    size_t base = (size_t)bh * SQ * DEP;

    // phase 0: Q into stage-0 bytes, extract frags, then overwrite
    tile_async(sb + 0, g_Q + base + (size_t)q0 * DEP, DEP, tid, 64);
    CP_COMMIT();
    CP_WAIT0();
    __syncthreads();

    uint32_t qh[4][4];
#pragma unroll
    for (int ks = 0; ks < 4; ks++)
        ldsm4(qh[ks][0], qh[ks][1], qh[ks][2], qh[ks][3], addrA(sb + 0, wid * 16, ks * 16, lid));
    __syncthreads();

    // phase 1: tiles 0 and 1 into stages 0 and 1 (separate groups)
    tile_async(sb + 0,    g_K + base, DEP, tid, KT);
    tile_async(sb + 8192, g_V + base, DEP, tid, KT);
    CP_COMMIT();
    tile_async(sb + A_SSZ + 0,    g_K + base + (size_t)KT * DEP, DEP, tid, KT);
    tile_async(sb + A_SSZ + 8192, g_V + base + (size_t)KT * DEP, DEP, tid, KT);
    CP_COMMIT();
    CP_WAIT1();           // stage 0 ready
    __syncthreads();

    float oacc[8][4];
#pragma unroll
    for (int nt = 0; nt < 8; nt++)
#pragma unroll
        for (int r = 0; r < 4; r++) oacc[nt][r] = 0.f;
    float lsacc[4] = {0.f, 0.f, 0.f, 0.f};   // row-sum accumulator (ones-MMA)

    const int NT = SQ / KT;
    for (int kt = 0; kt < NT; kt++) {
        uint32_t cur = sb + (uint32_t)(kt % 3) * A_SSZ;
        if (kt + 2 < NT) {
            uint32_t nxt = sb + (uint32_t)((kt + 2) % 3) * A_SSZ;
            size_t off = base + (size_t)(kt + 2) * KT * DEP;
            tile_async(nxt + 0,    g_K + off, DEP, tid, KT);
            tile_async(nxt + 8192, g_V + off, DEP, tid, KT);
            CP_COMMIT();
        }

        // MMA1: S[16 x 64] per warp, single fp16
        float s[8][4];
#pragma unroll
        for (int nt = 0; nt < 8; nt++)
#pragma unroll
            for (int r = 0; r < 4; r++) s[nt][r] = 0.f;
#pragma unroll
        for (int ks = 0; ks < 4; ks++) {
            int kc = ks * 16;
            uint32_t kb[16];
#pragma unroll
            for (int hf = 0; hf < 4; hf++)
                ldsm4(kb[hf * 4], kb[hf * 4 + 1], kb[hf * 4 + 2], kb[hf * 4 + 3],
                      addrB(cur + 0, hf * 16, kc, lid));
#pragma unroll
            for (int nt = 0; nt < 8; nt++)
                mmah(s[nt], qh[ks], kb[nt * 2], kb[nt * 2 + 1]);
        }

        // softmax + MMA2 per ks chunk; V ldsm hoisted ahead of the ex2/cvt chain
#pragma unroll
        for (int ks = 0; ks < 4; ks++) {
            uint32_t vb[16];
#pragma unroll
            for (int hf = 0; hf < 4; hf++)
                ldsm4t(vb[hf * 4], vb[hf * 4 + 1], vb[hf * 4 + 2], vb[hf * 4 + 3],
                       addrA(cur + 8192, ks * 16, hf * 16, lid));
            uint32_t pa[4];
            pa[0] = ex2h2(pkh2(s[2 * ks][0],     s[2 * ks][1]));
            pa[1] = ex2h2(pkh2(s[2 * ks][2],     s[2 * ks][3]));
            pa[2] = ex2h2(pkh2(s[2 * ks + 1][0], s[2 * ks + 1][1]));
            pa[3] = ex2h2(pkh2(s[2 * ks + 1][2], s[2 * ks + 1][3]));
            mmah(lsacc, pa, ONES2, ONES2);
#pragma unroll
            for (int nt = 0; nt < 8; nt++)
                mmah(oacc[nt], pa, vb[nt * 2], vb[nt * 2 + 1]);
        }

        if (kt < NT - 1) {
            if (kt < NT - 2) CP_WAIT1(); else CP_WAIT0();
            __syncthreads();
        }
    }

    float inv0 = 1.f / lsacc[0], inv1 = 1.f / lsacc[2];

    int b = bh >> 3, h = bh & (NH - 1);
    int r0 = q0 + wid * 16 + (lid >> 2);
#pragma unroll
    for (int nt = 0; nt < 8; nt++) {
        int col = nt * 8 + ((lid & 3) << 1);
        size_t idx = (((size_t)b * SQ + r0) * DM + h * DEP + col) >> 1;
        ((uint32_t*)g_AO)[idx] = pkh2(oacc[nt][0] * inv0, oacc[nt][1] * inv0);
        idx = (((size_t)b * SQ + r0 + 8) * DM + h * DEP + col) >> 1;
        ((uint32_t*)g_AO)[idx] = pkh2(oacc[nt][2] * inv1, oacc[nt][3] * inv1);
    }
}

// ---------------- launch ----------------
extern "C" void kernel_launch(void* const* d_in, const int* in_sizes, int n_in,
                              void* d_out, int out_size)
{
    const float* q   = (const float*)d_in[0];
    const float* k   = (const float*)d_in[1];
    const float* v   = (const float*)d_in[2];
    const float* pos = (const float*)d_in[3];
    const float* bq  = (const float*)d_in[5];
    const float* bk  = (const float*)d_in[7];
    const float* bv  = (const float*)d_in[9];
    const float* bf  = (const float*)d_in[11];
    float* out = (float*)d_out;

    cudaFuncSetAttribute(proj_mma, cudaFuncAttributeMaxDynamicSharedMemorySize, P_TOT);
    cudaFuncSetAttribute(attn_mma, cudaFuncAttributeMaxDynamicSharedMemorySize, A_TOT);

    split_all<<<dim3(NTOK * DM / 4 / 256, 7), 256>>>(q, k, v,
        (const float*)d_in[4], (const float*)d_in[6], (const float*)d_in[8], (const float*)d_in[10]);

    proj_mma<<<dim3(DM / 64, NTOK / 64, 3), 128, P_TOT>>>(bq, bk, bv, pos, nullptr, 1);

    attn_mma<<<dim3(SQ / 64, NBH), 128, A_TOT>>>();

    proj_mma<<<dim3(DM / 64, NTOK / 64, 1), 128, P_TOT>>>(bf, nullptr, nullptr, nullptr, out, 0);
}

// round 15
// speedup vs baseline: 1.0554x; 1.0554x over previous
#include <cuda_runtime.h>
#include <cuda_fp16.h>
#include <cstdint>

#define SQ    2048
#define DM    512
#define NH    8
#define DEP   64
#define BATCH 2
#define NTOK  (BATCH*SQ)
#define NBH   (BATCH*NH)

// ---------------- device scratch (fp16) ----------------
__device__ __half g_xq[NTOK*DM], g_xk[NTOK*DM], g_xv[NTOK*DM];
__device__ __half g_wq[DM*DM];
__device__ __half g_wk[DM*DM];
__device__ __half g_wv[DM*DM];
__device__ __half g_wf[DM*DM];
__device__ __half g_Q[NBH*SQ*DEP];   // pre-scaled log2e/8
__device__ __half g_K[NBH*SQ*DEP];   // pos folded in
__device__ __half g_V[NBH*SQ*DEP];
__device__ __half g_AO[NTOK*DM];

// ---------------- helpers ----------------
static __device__ __forceinline__ uint32_t smem_u32(const void* p) {
    uint32_t a;
    asm("{ .reg .u64 t; cvta.to.shared.u64 t, %1; cvt.u32.u64 %0, t; }" : "=r"(a) : "l"(p));
    return a;
}
static __device__ __forceinline__ uint32_t swz(uint32_t b) { return b ^ ((b >> 3) & 0x70); }

static __device__ __forceinline__ void cp16(uint32_t dst, const void* src) {
    asm volatile("cp.async.cg.shared.global [%0], [%1], 16;" :: "r"(dst), "l"(src));
}
#define CP_COMMIT() asm volatile("cp.async.commit_group;" ::: "memory")
#define CP_WAIT0()  asm volatile("cp.async.wait_group 0;" ::: "memory")
#define CP_WAIT1()  asm volatile("cp.async.wait_group 1;" ::: "memory")

static __device__ __forceinline__ void ldsm4(uint32_t& r0, uint32_t& r1, uint32_t& r2, uint32_t& r3, uint32_t a) {
    asm volatile("ldmatrix.sync.aligned.m8n8.x4.shared.b16 {%0,%1,%2,%3}, [%4];"
                 : "=r"(r0), "=r"(r1), "=r"(r2), "=r"(r3) : "r"(a));
}
static __device__ __forceinline__ void ldsm4t(uint32_t& r0, uint32_t& r1, uint32_t& r2, uint32_t& r3, uint32_t a) {
    asm volatile("ldmatrix.sync.aligned.m8n8.x4.trans.shared.b16 {%0,%1,%2,%3}, [%4];"
                 : "=r"(r0), "=r"(r1), "=r"(r2), "=r"(r3) : "r"(a));
}
static __device__ __forceinline__ void mmah(float* c, const uint32_t* a, uint32_t b0, uint32_t b1) {
    asm volatile("mma.sync.aligned.m16n8k16.row.col.f32.f16.f16.f32 "
                 "{%0,%1,%2,%3}, {%4,%5,%6,%7}, {%8,%9}, {%0,%1,%2,%3};"
                 : "+f"(c[0]), "+f"(c[1]), "+f"(c[2]), "+f"(c[3])
                 : "r"(a[0]), "r"(a[1]), "r"(a[2]), "r"(a[3]), "r"(b0), "r"(b1));
}
static __device__ __forceinline__ uint32_t addrA(uint32_t base, int row0, int col0, int lid) {
    int quad = lid >> 3, sub = lid & 7;
    int row = row0 + sub + ((quad & 1) << 3);
    int col = col0 + ((quad >> 1) << 3);
    return base + swz((uint32_t)(row * 128 + col * 2));
}
static __device__ __forceinline__ uint32_t addrB(uint32_t base, int row0, int col0, int lid) {
    int quad = lid >> 3, sub = lid & 7;
    int row = row0 + sub + ((quad >> 1) << 3);
    int col = col0 + ((quad & 1) << 3);
    return base + swz((uint32_t)(row * 128 + col * 2));
}
static __device__ __forceinline__ uint32_t pkh2(float v0, float v1) {
    __half2 h = __floats2half2_rn(v0, v1);
    return *(uint32_t*)&h;
}
static __device__ __forceinline__ uint32_t ex2h2(uint32_t x) {
    uint32_t r; asm("ex2.approx.f16x2 %0, %1;" : "=r"(r) : "r"(x)); return r;
}
// async copy [rows x 64] fp16 into SW128 smem tile; NT = thread count
template<int NTHREADS>
static __device__ __forceinline__ void tile_async(uint32_t dst, const __half* src,
                                                  int ldsrc, int tid, int rows) {
    int iters = rows * 8 / NTHREADS;
#pragma unroll
    for (int i = 0; i < iters; i++) {
        int g = i * NTHREADS + tid;
        int row = g >> 3, c16 = g & 7;
        cp16(dst + swz((uint32_t)(row * 128 + c16 * 16)), src + (size_t)row * ldsrc + c16 * 8);
    }
}

// ---------------- fp32 -> fp16 conversions (single launch) ----------------
__global__ void split_all(const float* __restrict__ q, const float* __restrict__ k,
                          const float* __restrict__ v, const float* __restrict__ wq,
                          const float* __restrict__ wk, const float* __restrict__ wv,
                          const float* __restrict__ wf) {
    int which = blockIdx.y;
    int i = blockIdx.x * blockDim.x + threadIdx.x;
    const float* x;
    __half* dst;
    int n4;
    switch (which) {
        case 0: x = q;  dst = g_xq; n4 = NTOK * DM / 4; break;
        case 1: x = k;  dst = g_xk; n4 = NTOK * DM / 4; break;
        case 2: x = v;  dst = g_xv; n4 = NTOK * DM / 4; break;
        case 3: x = wq; dst = g_wq; n4 = DM * DM / 4; break;
        case 4: x = wk; dst = g_wk; n4 = DM * DM / 4; break;
        case 5: x = wv; dst = g_wv; n4 = DM * DM / 4; break;
        default: x = wf; dst = g_wf; n4 = DM * DM / 4; break;
    }
    if (i < n4) {
        float4 v4 = ((const float4*)x)[i];
        uint2 h;
        h.x = pkh2(v4.x, v4.y);
        h.y = pkh2(v4.z, v4.w);
        ((uint2*)dst)[i] = h;
    }
}

// ---------------- projection GEMM (R12): M128 x N64, single MMA, 2-stage ----------------
// stage: A +0 (16K), B +16384 (8K); 24K/stage
#define P_STAGE 24576
#define P_TOT   (2*P_STAGE)

__global__ __launch_bounds__(128, 3) void proj_mma(
    const float* __restrict__ b1, const float* __restrict__ b2,
    const float* __restrict__ b3, const float* __restrict__ pos,
    float* __restrict__ outf, int mode_base)
{
    extern __shared__ char sm[];
    uint32_t sb = smem_u32(sm);
    int tid = threadIdx.x, wid = tid >> 5, lid = tid & 31;
    int m0 = blockIdx.y * 128, n0 = blockIdx.x * 64;
    int mode = mode_base ? (mode_base + (int)blockIdx.z) : 0;
    int wm = (wid & 1) * 64, wn = (wid >> 1) * 32;

    const __half *A, *B;
    const float* bias;
    switch (mode) {
        case 0: A = g_AO; B = g_wf; bias = b1; break;
        case 1: A = g_xq; B = g_wq; bias = b1; break;
        case 2: A = g_xk; B = g_wk; bias = b2; break;
        default: A = g_xv; B = g_wv; bias = b3; break;
    }

    float acc[4][4][4];
#pragma unroll
    for (int i = 0; i < 4; i++)
#pragma unroll
        for (int j = 0; j < 4; j++)
#pragma unroll
            for (int r = 0; r < 4; r++) acc[i][j][r] = 0.f;

    tile_async<128>(sb + 0,     A + (size_t)m0 * DM, DM, tid, 128);
    tile_async<128>(sb + 16384, B + (size_t)n0 * DM, DM, tid, 64);
    CP_COMMIT();
    CP_WAIT0();
    __syncthreads();

    for (int c = 0; c < 8; c++) {
        uint32_t cur = sb + (uint32_t)(c & 1) * P_STAGE;
        if (c < 7) {
            uint32_t nxt = sb + (uint32_t)((c + 1) & 1) * P_STAGE;
            int k1 = (c + 1) * 64;
            tile_async<128>(nxt + 0,     A + (size_t)m0 * DM + k1, DM, tid, 128);
            tile_async<128>(nxt + 16384, B + (size_t)n0 * DM + k1, DM, tid, 64);
            CP_COMMIT();
        }

#pragma unroll
        for (int ks = 0; ks < 4; ks++) {
            int kc = ks * 16;
            uint32_t ah[4][4];
#pragma unroll
            for (int mt = 0; mt < 4; mt++)
                ldsm4(ah[mt][0], ah[mt][1], ah[mt][2], ah[mt][3], addrA(cur + 0, wm + mt * 16, kc, lid));
            uint32_t bh[8];
#pragma unroll
            for (int hf = 0; hf < 2; hf++)
                ldsm4(bh[hf * 4], bh[hf * 4 + 1], bh[hf * 4 + 2], bh[hf * 4 + 3],
                      addrB(cur + 16384, wn + hf * 16, kc, lid));
#pragma unroll
            for (int mt = 0; mt < 4; mt++)
#pragma unroll
                for (int nt = 0; nt < 4; nt++)
                    mmah(acc[mt][nt], ah[mt], bh[nt * 2], bh[nt * 2 + 1]);
        }
        if (c < 7) {
            CP_WAIT0();
            __syncthreads();
        }
    }

    const float SC = 0.180336880111120429f;  // log2(e)/8
#pragma unroll
    for (int mt = 0; mt < 4; mt++) {
        int r0g = m0 + wm + mt * 16 + (lid >> 2);
#pragma unroll
        for (int nt = 0; nt < 4; nt++) {
            int og = n0 + wn + nt * 8 + ((lid & 3) << 1);
            float b0 = bias[og], b1v = bias[og + 1];
#pragma unroll
            for (int half = 0; half < 2; half++) {
                int n = r0g + half * 8;
                float v0 = acc[mt][nt][half * 2]     + b0;
                float v1 = acc[mt][nt][half * 2 + 1] + b1v;
                if (mode == 0) {
                    outf[(size_t)n * DM + og]     = v0;
                    outf[(size_t)n * DM + og + 1] = v1;
                } else {
                    int bb = n >> 11, s = n & (SQ - 1);
                    int h = og >> 6, d = og & 63;
                    if (mode == 2) { v0 += pos[s * DEP + d]; v1 += pos[s * DEP + d + 1]; }
                    if (mode == 1) { v0 *= SC; v1 *= SC; }
                    size_t idx = ((((size_t)(bb * NH + h) * SQ) + s) * DEP + d) >> 1;
                    __half* dst = (mode == 1) ? g_Q : ((mode == 2) ? g_K : g_V);
                    ((uint32_t*)dst)[idx] = pkh2(v0, v1);
                }
            }
        }
    }
}

// ---------------- flash attention: 256 threads, q-tile 128, 2 CTA/SM, 3-stage ----------------
#define A_SSZ 16384
#define A_TOT (3*A_SSZ)
#define KT 64
#define ONES2 0x3C003C00u   // (1.0h, 1.0h)

__global__ __launch_bounds__(256, 2) void attn_mma() {
    extern __shared__ char sm[];
    uint32_t sb = smem_u32(sm);
    int tid = threadIdx.x, wid = tid >> 5, lid = tid & 31;
    int bh = blockIdx.y, q0 = blockIdx.x * 128;
    size_t base = (size_t)bh * SQ * DEP;

    // phase 0: Q (128 rows = 16KB) into stage-0 bytes, extract frags, then overwrite
    tile_async<256>(sb + 0, g_Q + base + (size_t)q0 * DEP, DEP, tid, 128);
    CP_COMMIT();
    CP_WAIT0();
    __syncthreads();

    uint32_t qh[4][4];
#pragma unroll
    for (int ks = 0; ks < 4; ks++)
        ldsm4(qh[ks][0], qh[ks][1], qh[ks][2], qh[ks][3], addrA(sb + 0, wid * 16, ks * 16, lid));
    __syncthreads();

    // phase 1: tiles 0 and 1 into stages 0 and 1 (separate groups)
    tile_async<256>(sb + 0,    g_K + base, DEP, tid, KT);
    tile_async<256>(sb + 8192, g_V + base, DEP, tid, KT);
    CP_COMMIT();
    tile_async<256>(sb + A_SSZ + 0,    g_K + base + (size_t)KT * DEP, DEP, tid, KT);
    tile_async<256>(sb + A_SSZ + 8192, g_V + base + (size_t)KT * DEP, DEP, tid, KT);
    CP_COMMIT();
    CP_WAIT1();           // stage 0 ready
    __syncthreads();

    float oacc[8][4];
#pragma unroll
    for (int nt = 0; nt < 8; nt++)
#pragma unroll
        for (int r = 0; r < 4; r++) oacc[nt][r] = 0.f;
    float lsacc[4] = {0.f, 0.f, 0.f, 0.f};

    const int NT = SQ / KT;
    for (int kt = 0; kt < NT; kt++) {
        uint32_t cur = sb + (uint32_t)(kt % 3) * A_SSZ;
        if (kt + 2 < NT) {
            uint32_t nxt = sb + (uint32_t)((kt + 2) % 3) * A_SSZ;
            size_t off = base + (size_t)(kt + 2) * KT * DEP;
            tile_async<256>(nxt + 0,    g_K + off, DEP, tid, KT);
            tile_async<256>(nxt + 8192, g_V + off, DEP, tid, KT);
            CP_COMMIT();
        }

        // MMA1: S[16 x 64] per warp, single fp16
        float s[8][4];
#pragma unroll
        for (int nt = 0; nt < 8; nt++)
#pragma unroll
            for (int r = 0; r < 4; r++) s[nt][r] = 0.f;
#pragma unroll
        for (int ks = 0; ks < 4; ks++) {
            int kc = ks * 16;
            uint32_t kb[16];
#pragma unroll
            for (int hf = 0; hf < 4; hf++)
                ldsm4(kb[hf * 4], kb[hf * 4 + 1], kb[hf * 4 + 2], kb[hf * 4 + 3],
                      addrB(cur + 0, hf * 16, kc, lid));
#pragma unroll
            for (int nt = 0; nt < 8; nt++)
                mmah(s[nt], qh[ks], kb[nt * 2], kb[nt * 2 + 1]);
        }

        // softmax + MMA2 per ks chunk; V ldsm hoisted ahead of the ex2/cvt chain
#pragma unroll
        for (int ks = 0; ks < 4; ks++) {
            uint32_t vb[16];
#pragma unroll
            for (int hf = 0; hf < 4; hf++)
                ldsm4t(vb[hf * 4], vb[hf * 4 + 1], vb[hf * 4 + 2], vb[hf * 4 + 3],
                       addrA(cur + 8192, ks * 16, hf * 16, lid));
            uint32_t pa[4];
            pa[0] = ex2h2(pkh2(s[2 * ks][0],     s[2 * ks][1]));
            pa[1] = ex2h2(pkh2(s[2 * ks][2],     s[2 * ks][3]));
            pa[2] = ex2h2(pkh2(s[2 * ks + 1][0], s[2 * ks + 1][1]));
            pa[3] = ex2h2(pkh2(s[2 * ks + 1][2], s[2 * ks + 1][3]));
            mmah(lsacc, pa, ONES2, ONES2);
#pragma unroll
            for (int nt = 0; nt < 8; nt++)
                mmah(oacc[nt], pa, vb[nt * 2], vb[nt * 2 + 1]);
        }

        if (kt < NT - 1) {
            if (kt < NT - 2) CP_WAIT1(); else CP_WAIT0();
            __syncthreads();
        }
    }

    float inv0 = 1.f / lsacc[0], inv1 = 1.f / lsacc[2];

    int b = bh >> 3, h = bh & (NH - 1);
    int r0 = q0 + wid * 16 + (lid >> 2);
#pragma unroll
    for (int nt = 0; nt < 8; nt++) {
        int col = nt * 8 + ((lid & 3) << 1);
        size_t idx = (((size_t)b * SQ + r0) * DM + h * DEP + col) >> 1;
        ((uint32_t*)g_AO)[idx] = pkh2(oacc[nt][0] * inv0, oacc[nt][1] * inv0);
        idx = (((size_t)b * SQ + r0 + 8) * DM + h * DEP + col) >> 1;
        ((uint32_t*)g_AO)[idx] = pkh2(oacc[nt][2] * inv1, oacc[nt][3] * inv1);
    }
}

// ---------------- launch ----------------
extern "C" void kernel_launch(void* const* d_in, const int* in_sizes, int n_in,
                              void* d_out, int out_size)
{
    const float* q   = (const float*)d_in[0];
    const float* k   = (const float*)d_in[1];
    const float* v   = (const float*)d_in[2];
    const float* pos = (const float*)d_in[3];
    const float* bq  = (const float*)d_in[5];
    const float* bk  = (const float*)d_in[7];
    const float* bv  = (const float*)d_in[9];
    const float* bf  = (const float*)d_in[11];
    float* out = (float*)d_out;

    cudaFuncSetAttribute(proj_mma, cudaFuncAttributeMaxDynamicSharedMemorySize, P_TOT);
    cudaFuncSetAttribute(attn_mma, cudaFuncAttributeMaxDynamicSharedMemorySize, A_TOT);

    split_all<<<dim3(NTOK * DM / 4 / 256, 7), 256>>>(q, k, v,
        (const float*)d_in[4], (const float*)d_in[6], (const float*)d_in[8], (const float*)d_in[10]);

    proj_mma<<<dim3(DM / 64, NTOK / 128, 3), 128, P_TOT>>>(bq, bk, bv, pos, nullptr, 1);

    attn_mma<<<dim3(SQ / 128, NBH), 256, A_TOT>>>();

    proj_mma<<<dim3(DM / 64, NTOK / 128, 1), 128, P_TOT>>>(bf, nullptr, nullptr, nullptr, out, 0);
}

// round 17
// speedup vs baseline: 1.1382x; 1.0785x over previous
#include <cuda_runtime.h>
#include <cuda_fp16.h>
#include <cstdint>

#define SQ    2048
#define DM    512
#define NH    8
#define DEP   64
#define BATCH 2
#define NTOK  (BATCH*SQ)
#define NBH   (BATCH*NH)

// ---------------- device scratch (fp16) ----------------
__device__ __half g_xq[NTOK*DM], g_xk[NTOK*DM], g_xv[NTOK*DM];
__device__ __half g_wq[DM*DM];
__device__ __half g_wk[DM*DM];
__device__ __half g_wv[DM*DM];
__device__ __half g_wf[DM*DM];
__device__ __half g_Q[NBH*SQ*DEP];   // pre-scaled log2e/8
__device__ __half g_K[NBH*SQ*DEP];   // pos folded in
__device__ __half g_V[NBH*SQ*DEP];
__device__ __half g_AO[NTOK*DM];

// ---------------- helpers ----------------
static __device__ __forceinline__ uint32_t smem_u32(const void* p) {
    uint32_t a;
    asm("{ .reg .u64 t; cvta.to.shared.u64 t, %1; cvt.u32.u64 %0, t; }" : "=r"(a) : "l"(p));
    return a;
}
static __device__ __forceinline__ uint32_t swz(uint32_t b) { return b ^ ((b >> 3) & 0x70); }

static __device__ __forceinline__ void cp16(uint32_t dst, const void* src) {
    asm volatile("cp.async.cg.shared.global [%0], [%1], 16;" :: "r"(dst), "l"(src));
}
#define CP_COMMIT() asm volatile("cp.async.commit_group;" ::: "memory")
#define CP_WAIT0()  asm volatile("cp.async.wait_group 0;" ::: "memory")
#define CP_WAIT1()  asm volatile("cp.async.wait_group 1;" ::: "memory")

static __device__ __forceinline__ void ldsm4(uint32_t& r0, uint32_t& r1, uint32_t& r2, uint32_t& r3, uint32_t a) {
    asm volatile("ldmatrix.sync.aligned.m8n8.x4.shared.b16 {%0,%1,%2,%3}, [%4];"
                 : "=r"(r0), "=r"(r1), "=r"(r2), "=r"(r3) : "r"(a));
}
static __device__ __forceinline__ void ldsm4t(uint32_t& r0, uint32_t& r1, uint32_t& r2, uint32_t& r3, uint32_t a) {
    asm volatile("ldmatrix.sync.aligned.m8n8.x4.trans.shared.b16 {%0,%1,%2,%3}, [%4];"
                 : "=r"(r0), "=r"(r1), "=r"(r2), "=r"(r3) : "r"(a));
}
static __device__ __forceinline__ void mmah(float* c, const uint32_t* a, uint32_t b0, uint32_t b1) {
    asm volatile("mma.sync.aligned.m16n8k16.row.col.f32.f16.f16.f32 "
                 "{%0,%1,%2,%3}, {%4,%5,%6,%7}, {%8,%9}, {%0,%1,%2,%3};"
                 : "+f"(c[0]), "+f"(c[1]), "+f"(c[2]), "+f"(c[3])
                 : "r"(a[0]), "r"(a[1]), "r"(a[2]), "r"(a[3]), "r"(b0), "r"(b1));
}
static __device__ __forceinline__ uint32_t addrA(uint32_t base, int row0, int col0, int lid) {
    int quad = lid >> 3, sub = lid & 7;
    int row = row0 + sub + ((quad & 1) << 3);
    int col = col0 + ((quad >> 1) << 3);
    return base + swz((uint32_t)(row * 128 + col * 2));
}
static __device__ __forceinline__ uint32_t addrB(uint32_t base, int row0, int col0, int lid) {
    int quad = lid >> 3, sub = lid & 7;
    int row = row0 + sub + ((quad >> 1) << 3);
    int col = col0 + ((quad & 1) << 3);
    return base + swz((uint32_t)(row * 128 + col * 2));
}
static __device__ __forceinline__ uint32_t pkh2(float v0, float v1) {
    __half2 h = __floats2half2_rn(v0, v1);
    return *(uint32_t*)&h;
}
static __device__ __forceinline__ uint32_t ex2h2(uint32_t x) {
    uint32_t r; asm("ex2.approx.f16x2 %0, %1;" : "=r"(r) : "r"(x)); return r;
}
// async copy [rows x 64] fp16 into SW128 smem tile; NT = thread count
template<int NTHREADS>
static __device__ __forceinline__ void tile_async(uint32_t dst, const __half* src,
                                                  int ldsrc, int tid, int rows) {
    int iters = rows * 8 / NTHREADS;
#pragma unroll
    for (int i = 0; i < iters; i++) {
        int g = i * NTHREADS + tid;
        int row = g >> 3, c16 = g & 7;
        cp16(dst + swz((uint32_t)(row * 128 + c16 * 16)), src + (size_t)row * ldsrc + c16 * 8);
    }
}

// ---------------- fp32 -> fp16 conversions (single launch) ----------------
__global__ void split_all(const float* __restrict__ q, const float* __restrict__ k,
                          const float* __restrict__ v, const float* __restrict__ wq,
                          const float* __restrict__ wk, const float* __restrict__ wv,
                          const float* __restrict__ wf) {
    int which = blockIdx.y;
    int i = blockIdx.x * blockDim.x + threadIdx.x;
    const float* x;
    __half* dst;
    int n4;
    switch (which) {
        case 0: x = q;  dst = g_xq; n4 = NTOK * DM / 4; break;
        case 1: x = k;  dst = g_xk; n4 = NTOK * DM / 4; break;
        case 2: x = v;  dst = g_xv; n4 = NTOK * DM / 4; break;
        case 3: x = wq; dst = g_wq; n4 = DM * DM / 4; break;
        case 4: x = wk; dst = g_wk; n4 = DM * DM / 4; break;
        case 5: x = wv; dst = g_wv; n4 = DM * DM / 4; break;
        default: x = wf; dst = g_wf; n4 = DM * DM / 4; break;
    }
    if (i < n4) {
        float4 v4 = ((const float4*)x)[i];
        uint2 h;
        h.x = pkh2(v4.x, v4.y);
        h.y = pkh2(v4.z, v4.w);
        ((uint2*)dst)[i] = h;
    }
}

// ---------------- projection GEMM (R12): M128 x N64, single MMA, 2-stage ----------------
#define P_STAGE 24576
#define P_TOT   (2*P_STAGE)

__global__ __launch_bounds__(128, 3) void proj_mma(
    const float* __restrict__ b1, const float* __restrict__ b2,
    const float* __restrict__ b3, const float* __restrict__ pos,
    float* __restrict__ outf, int mode_base)
{
    extern __shared__ char sm[];
    uint32_t sb = smem_u32(sm);
    int tid = threadIdx.x, wid = tid >> 5, lid = tid & 31;
    int m0 = blockIdx.y * 128, n0 = blockIdx.x * 64;
    int mode = mode_base ? (mode_base + (int)blockIdx.z) : 0;
    int wm = (wid & 1) * 64, wn = (wid >> 1) * 32;

    const __half *A, *B;
    const float* bias;
    switch (mode) {
        case 0: A = g_AO; B = g_wf; bias = b1; break;
        case 1: A = g_xq; B = g_wq; bias = b1; break;
        case 2: A = g_xk; B = g_wk; bias = b2; break;
        default: A = g_xv; B = g_wv; bias = b3; break;
    }

    float acc[4][4][4];
#pragma unroll
    for (int i = 0; i < 4; i++)
#pragma unroll
        for (int j = 0; j < 4; j++)
#pragma unroll
            for (int r = 0; r < 4; r++) acc[i][j][r] = 0.f;

    tile_async<128>(sb + 0,     A + (size_t)m0 * DM, DM, tid, 128);
    tile_async<128>(sb + 16384, B + (size_t)n0 * DM, DM, tid, 64);
    CP_COMMIT();
    CP_WAIT0();
    __syncthreads();

    for (int c = 0; c < 8; c++) {
        uint32_t cur = sb + (uint32_t)(c & 1) * P_STAGE;
        if (c < 7) {
            uint32_t nxt = sb + (uint32_t)((c + 1) & 1) * P_STAGE;
            int k1 = (c + 1) * 64;
            tile_async<128>(nxt + 0,     A + (size_t)m0 * DM + k1, DM, tid, 128);
            tile_async<128>(nxt + 16384, B + (size_t)n0 * DM + k1, DM, tid, 64);
            CP_COMMIT();
        }

#pragma unroll
        for (int ks = 0; ks < 4; ks++) {
            int kc = ks * 16;
            uint32_t ah[4][4];
#pragma unroll
            for (int mt = 0; mt < 4; mt++)
                ldsm4(ah[mt][0], ah[mt][1], ah[mt][2], ah[mt][3], addrA(cur + 0, wm + mt * 16, kc, lid));
            uint32_t bh[8];
#pragma unroll
            for (int hf = 0; hf < 2; hf++)
                ldsm4(bh[hf * 4], bh[hf * 4 + 1], bh[hf * 4 + 2], bh[hf * 4 + 3],
                      addrB(cur + 16384, wn + hf * 16, kc, lid));
#pragma unroll
            for (int mt = 0; mt < 4; mt++)
#pragma unroll
                for (int nt = 0; nt < 4; nt++)
                    mmah(acc[mt][nt], ah[mt], bh[nt * 2], bh[nt * 2 + 1]);
        }
        if (c < 7) {
            CP_WAIT0();
            __syncthreads();
        }
    }

    const float SC = 0.180336880111120429f;  // log2(e)/8
#pragma unroll
    for (int mt = 0; mt < 4; mt++) {
        int r0g = m0 + wm + mt * 16 + (lid >> 2);
#pragma unroll
        for (int nt = 0; nt < 4; nt++) {
            int og = n0 + wn + nt * 8 + ((lid & 3) << 1);
            float b0 = bias[og], b1v = bias[og + 1];
#pragma unroll
            for (int half = 0; half < 2; half++) {
                int n = r0g + half * 8;
                float v0 = acc[mt][nt][half * 2]     + b0;
                float v1 = acc[mt][nt][half * 2 + 1] + b1v;
                if (mode == 0) {
                    outf[(size_t)n * DM + og]     = v0;
                    outf[(size_t)n * DM + og + 1] = v1;
                } else {
                    int bb = n >> 11, s = n & (SQ - 1);
                    int h = og >> 6, d = og & 63;
                    if (mode == 2) { v0 += pos[s * DEP + d]; v1 += pos[s * DEP + d + 1]; }
                    if (mode == 1) { v0 *= SC; v1 *= SC; }
                    size_t idx = ((((size_t)(bb * NH + h) * SQ) + s) * DEP + d) >> 1;
                    __half* dst = (mode == 1) ? g_Q : ((mode == 2) ? g_K : g_V);
                    ((uint32_t*)dst)[idx] = pkh2(v0, v1);
                }
            }
        }
    }
}

// ---------------- flash attention: 4 warps x 32 q-rows (2 m-tiles/warp) ----------------
// smem traffic per FLOP halved: kb/vb fragments reused across both m-tiles.
#define A_SSZ 16384
#define A_TOT (3*A_SSZ)
#define KT 64
#define ONES2 0x3C003C00u   // (1.0h, 1.0h)

__global__ __launch_bounds__(128, 2) void attn_mma() {
    extern __shared__ char sm[];
    uint32_t sb = smem_u32(sm);
    int tid = threadIdx.x, wid = tid >> 5, lid = tid & 31;
    int bh = blockIdx.y, q0 = blockIdx.x * 128;
    size_t base = (size_t)bh * SQ * DEP;

    // phase 0: Q (128 rows = 16KB) into stage-0 bytes, extract frags, then overwrite
    tile_async<128>(sb + 0, g_Q + base + (size_t)q0 * DEP, DEP, tid, 128);
    CP_COMMIT();
    CP_WAIT0();
    __syncthreads();

    uint32_t qh[2][4][4];   // [m-tile][ks][frag]
#pragma unroll
    for (int mt = 0; mt < 2; mt++)
#pragma unroll
        for (int ks = 0; ks < 4; ks++)
            ldsm4(qh[mt][ks][0], qh[mt][ks][1], qh[mt][ks][2], qh[mt][ks][3],
                  addrA(sb + 0, wid * 32 + mt * 16, ks * 16, lid));
    __syncthreads();

    // phase 1: tiles 0 and 1 into stages 0 and 1 (separate groups)
    tile_async<128>(sb + 0,    g_K + base, DEP, tid, KT);
    tile_async<128>(sb + 8192, g_V + base, DEP, tid, KT);
    CP_COMMIT();
    tile_async<128>(sb + A_SSZ + 0,    g_K + base + (size_t)KT * DEP, DEP, tid, KT);
    tile_async<128>(sb + A_SSZ + 8192, g_V + base + (size_t)KT * DEP, DEP, tid, KT);
    CP_COMMIT();
    CP_WAIT1();           // stage 0 ready
    __syncthreads();

    float oacc[2][8][4];
#pragma unroll
    for (int mt = 0; mt < 2; mt++)
#pragma unroll
        for (int nt = 0; nt < 8; nt++)
#pragma unroll
            for (int r = 0; r < 4; r++) oacc[mt][nt][r] = 0.f;
    float lsacc[2][4];
#pragma unroll
    for (int mt = 0; mt < 2; mt++)
#pragma unroll
        for (int r = 0; r < 4; r++) lsacc[mt][r] = 0.f;

    const int NT = SQ / KT;
    for (int kt = 0; kt < NT; kt++) {
        uint32_t cur = sb + (uint32_t)(kt % 3) * A_SSZ;
        if (kt + 2 < NT) {
            uint32_t nxt = sb + (uint32_t)((kt + 2) % 3) * A_SSZ;
            size_t off = base + (size_t)(kt + 2) * KT * DEP;
            tile_async<128>(nxt + 0,    g_K + off, DEP, tid, KT);
            tile_async<128>(nxt + 8192, g_V + off, DEP, tid, KT);
            CP_COMMIT();
        }

        // MMA1: S[32 x 64] per warp (2 m-tiles share each K fragment)
        float s[2][8][4];
#pragma unroll
        for (int mt = 0; mt < 2; mt++)
#pragma unroll
            for (int nt = 0; nt < 8; nt++)
#pragma unroll
                for (int r = 0; r < 4; r++) s[mt][nt][r] = 0.f;
#pragma unroll
        for (int ks = 0; ks < 4; ks++) {
            int kc = ks * 16;
            uint32_t kb[16];
#pragma unroll
            for (int hf = 0; hf < 4; hf++)
                ldsm4(kb[hf * 4], kb[hf * 4 + 1], kb[hf * 4 + 2], kb[hf * 4 + 3],
                      addrB(cur + 0, hf * 16, kc, lid));
#pragma unroll
            for (int mt = 0; mt < 2; mt++)
#pragma unroll
                for (int nt = 0; nt < 8; nt++)
                    mmah(s[mt][nt], qh[mt][ks], kb[nt * 2], kb[nt * 2 + 1]);
        }

        // softmax + MMA2 per ks chunk; V fragments shared across both m-tiles
#pragma unroll
        for (int ks = 0; ks < 4; ks++) {
            uint32_t vb[16];
#pragma unroll
            for (int hf = 0; hf < 4; hf++)
                ldsm4t(vb[hf * 4], vb[hf * 4 + 1], vb[hf * 4 + 2], vb[hf * 4 + 3],
                       addrA(cur + 8192, ks * 16, hf * 16, lid));
#pragma unroll
            for (int mt = 0; mt < 2; mt++) {
                uint32_t pa[4];
                pa[0] = ex2h2(pkh2(s[mt][2 * ks][0],     s[mt][2 * ks][1]));
                pa[1] = ex2h2(pkh2(s[mt][2 * ks][2],     s[mt][2 * ks][3]));
                pa[2] = ex2h2(pkh2(s[mt][2 * ks + 1][0], s[mt][2 * ks + 1][1]));
                pa[3] = ex2h2(pkh2(s[mt][2 * ks + 1][2], s[mt][2 * ks + 1][3]));
                mmah(lsacc[mt], pa, ONES2, ONES2);
#pragma unroll
                for (int nt = 0; nt < 8; nt++)
                    mmah(oacc[mt][nt], pa, vb[nt * 2], vb[nt * 2 + 1]);
            }
        }

        if (kt < NT - 1) {
            if (kt < NT - 2) CP_WAIT1(); else CP_WAIT0();
            __syncthreads();
        }
    }

    int b = bh >> 3, h = bh & (NH - 1);
#pragma unroll
    for (int mt = 0; mt < 2; mt++) {
        float inv0 = 1.f / lsacc[mt][0], inv1 = 1.f / lsacc[mt][2];
        int r0 = q0 + wid * 32 + mt * 16 + (lid >> 2);
#pragma unroll
        for (int nt = 0; nt < 8; nt++) {
            int col = nt * 8 + ((lid & 3) << 1);
            size_t idx = (((size_t)b * SQ + r0) * DM + h * DEP + col) >> 1;
            ((uint32_t*)g_AO)[idx] = pkh2(oacc[mt][nt][0] * inv0, oacc[mt][nt][1] * inv0);
            idx = (((size_t)b * SQ + r0 + 8) * DM + h * DEP + col) >> 1;
            ((uint32_t*)g_AO)[idx] = pkh2(oacc[mt][nt][2] * inv1, oacc[mt][nt][3] * inv1);
        }
    }
}

// ---------------- launch ----------------
extern "C" void kernel_launch(void* const* d_in, const int* in_sizes, int n_in,
                              void* d_out, int out_size)
{
    const float* q   = (const float*)d_in[0];
    const float* k   = (const float*)d_in[1];
    const float* v   = (const float*)d_in[2];
    const float* pos = (const float*)d_in[3];
    const float* bq  = (const float*)d_in[5];
    const float* bk  = (const float*)d_in[7];
    const float* bv  = (const float*)d_in[9];
    const float* bf  = (const float*)d_in[11];
    float* out = (float*)d_out;

    cudaFuncSetAttribute(proj_mma, cudaFuncAttributeMaxDynamicSharedMemorySize, P_TOT);
    cudaFuncSetAttribute(attn_mma, cudaFuncAttributeMaxDynamicSharedMemorySize, A_TOT);

    split_all<<<dim3(NTOK * DM / 4 / 256, 7), 256>>>(q, k, v,
        (const float*)d_in[4], (const float*)d_in[6], (const float*)d_in[8], (const float*)d_in[10]);

    proj_mma<<<dim3(DM / 64, NTOK / 128, 3), 128, P_TOT>>>(bq, bk, bv, pos, nullptr, 1);

    attn_mma<<<dim3(SQ / 128, NBH), 128, A_TOT>>>();

    proj_mma<<<dim3(DM / 64, NTOK / 128, 1), 128, P_TOT>>>(bf, nullptr, nullptr, nullptr, out, 0);
}